// round 12
// baseline (speedup 1.0000x reference)
#include <cuda_runtime.h>
#include <cuda_bf16.h>
#include <cstdint>
#include <math.h>

// ---------------------------------------------------------------------------
// MultiHeadAttention (B=8, T=1024, E=768, H=12)
// Primary: split-bf16 GEMMs via mma.sync.m16n8k16, fragments loaded by
//   DIRECT GLOBAL LOADS (no SMEM, no ldmatrix) -- addresses straight from
//   the PTX fragment tables. C = Ahi@Bhi + Alo@Bhi + Ahi@Blo (fp32 acc).
// Diagnostics (read via dur_us when the guard fires):
//   +3ms  : split/transpose buffers disagree with raw inputs
//   +6ms  : mma all-ones test failed
//   +12ms : mma e(0,0) positional test failed (c0 mapping)
//   +24ms : mma row+8 (a1->c2) or k+8 (a2/b1) test failed
// Safety: numerical check of stage-0 V; fp32 SIMT pipeline guarded by g_ok.
// ---------------------------------------------------------------------------

#define AL __align__(256)
__device__ AL __nv_bfloat16 g_xhi[8192 * 768];
__device__ AL __nv_bfloat16 g_xlo[8192 * 768];
__device__ AL __nv_bfloat16 g_WQth[12 * 768 * 768], g_WQtl[12 * 768 * 768];
__device__ AL __nv_bfloat16 g_WKth[12 * 768 * 768], g_WKtl[12 * 768 * 768];
__device__ AL __nv_bfloat16 g_WVth[12 * 768 * 768], g_WVtl[12 * 768 * 768];
__device__ AL __nv_bfloat16 g_WOth[768 * 9216], g_WOtl[768 * 9216];
__device__ AL __nv_bfloat16 g_Qhi[96 * 786432], g_Qlo[96 * 786432];
__device__ AL __nv_bfloat16 g_Khi[96 * 786432], g_Klo[96 * 786432];
__device__ AL __nv_bfloat16 g_Kthi[96 * 786432], g_Ktlo[96 * 786432];
__device__ AL __nv_bfloat16 g_Vhi[96 * 786432], g_Vlo[96 * 786432];
__device__ AL __nv_bfloat16 g_Vthi[96 * 786432], g_Vtlo[96 * 786432];
__device__ AL float         g_S[96 * 1048576];
__device__ AL __nv_bfloat16 g_Phi[96 * 1048576], g_Plo[96 * 1048576];
__device__ AL __nv_bfloat16 g_Zhi[96 * 786432], g_Zlo[96 * 786432];
// SIMT-fallback scratch
__device__ AL float g_Qf[96 * 786432];
__device__ AL float g_Kf[96 * 786432];
__device__ AL float g_Vf[96 * 786432];
__device__ AL float g_Zf[96 * 786432];
__device__ int g_ok;
__device__ int g_diag_buf;
__device__ int g_diag_mma;

// ------------------------------ helpers ------------------------------------
__device__ __forceinline__ void mma16816(float* c, const uint32_t* a, const uint32_t* b) {
    asm volatile(
        "mma.sync.aligned.m16n8k16.row.col.f32.bf16.bf16.f32 "
        "{%0,%1,%2,%3}, {%4,%5,%6,%7}, {%8,%9}, {%0,%1,%2,%3};"
        : "+f"(c[0]), "+f"(c[1]), "+f"(c[2]), "+f"(c[3])
        : "r"(a[0]), "r"(a[1]), "r"(a[2]), "r"(a[3]), "r"(b[0]), "r"(b[1]));
}

// ------------------------------- MMA GEMM ----------------------------------
// Block 256 thr (8 warps, 2x4 grid of 64x32 warp tiles), tile 128x128.
// Fragments by direct LDG: correct-by-construction addressing.
__global__ __launch_bounds__(256)
void mma_gemm(int mode, float* __restrict__ out)
{
    const int tid = threadIdx.x;
    const int lane = tid & 31;
    const int warp = tid >> 5;

    const __nv_bfloat16 *Ah, *Al, *Bh, *Bl;
    __nv_bfloat16 *Ch = nullptr, *Cl = nullptr;
    float* Cf = nullptr;
    long lda, ldb, ldc;
    int K;
    const int z = blockIdx.z;

    if (mode == 0) {
        int which = z / 12, h = z - which * 12;
        Ah = g_xhi; Al = g_xlo; lda = 768; K = 768;
        if (which == 0)      { Bh = g_WQth; Bl = g_WQtl; Ch = g_Qhi; Cl = g_Qlo; }
        else if (which == 1) { Bh = g_WKth; Bl = g_WKtl; Ch = g_Khi; Cl = g_Klo; }
        else                 { Bh = g_WVth; Bl = g_WVtl; Ch = g_Vhi; Cl = g_Vlo; }
        Bh += (long)h * 589824;  Bl += (long)h * 589824;  ldb = 768;
        Ch += (long)h * 6291456; Cl += (long)h * 6291456; ldc = 768;
    } else if (mode == 1) {
        Ah = g_Qhi  + (long)z * 786432; Al = g_Qlo  + (long)z * 786432; lda = 768; K = 768;
        Bh = g_Kthi + (long)z * 786432; Bl = g_Ktlo + (long)z * 786432; ldb = 768;
        Cf = g_S + (long)z * 1048576; ldc = 1024;
    } else if (mode == 2) {
        Ah = g_Phi  + (long)z * 1048576; Al = g_Plo  + (long)z * 1048576; lda = 1024; K = 1024;
        Bh = g_Vthi + (long)z * 786432;  Bl = g_Vtlo + (long)z * 786432;  ldb = 1024;
        int h = z >> 3, b = z & 7;
        Ch = g_Zhi + (long)(b * 12 + h) * 786432;
        Cl = g_Zlo + (long)(b * 12 + h) * 786432; ldc = 768;
    } else {
        Ah = g_Zhi; Al = g_Zlo; lda = 9216; K = 9216;
        Bh = g_WOth; Bl = g_WOtl; ldb = 9216;
        Cf = out; ldc = 768;
    }
    const bool split = (Ch != nullptr);

    const long row0 = (long)blockIdx.y * 128;
    const long col0 = (long)blockIdx.x * 128;
    Ah += row0 * lda; Al += row0 * lda;
    Bh += col0 * ldb; Bl += col0 * ldb;

    const int mb = (warp >> 2) * 64;
    const int nb = (warp & 3) * 32;
    const int fg = lane >> 2;     // groupID
    const int ft = lane & 3;      // threadID_in_group

    float acc[4][4][4];
#pragma unroll
    for (int i = 0; i < 4; i++)
#pragma unroll
        for (int j = 0; j < 4; j++)
#pragma unroll
            for (int q = 0; q < 4; q++) acc[i][j][q] = 0.0f;

    // per-thread row base pointers (hoisted)
    const __nv_bfloat16* aRowH[4];
    const __nv_bfloat16* aRowL[4];
    const __nv_bfloat16* bRowH[4];
    const __nv_bfloat16* bRowL[4];
#pragma unroll
    for (int fm = 0; fm < 4; fm++) {
        aRowH[fm] = Ah + (long)(mb + fm * 16 + fg) * lda;
        aRowL[fm] = Al + (long)(mb + fm * 16 + fg) * lda;
    }
#pragma unroll
    for (int fn = 0; fn < 4; fn++) {
        bRowH[fn] = Bh + (long)(nb + fn * 8 + fg) * ldb;
        bRowL[fn] = Bl + (long)(nb + fn * 8 + fg) * ldb;
    }
    const long a8 = 8 * lda;   // +8 rows

    const int nks = K >> 4;
    for (int ks = 0; ks < nks; ks++) {
        const int klo = (ks << 4) + 2 * ft;   // elements
        const int khi = klo + 8;
        uint32_t ahf[4][4], alf[4][4], bhf[4][2], blf[4][2];
#pragma unroll
        for (int fm = 0; fm < 4; fm++) {
            ahf[fm][0] = *(const uint32_t*)(aRowH[fm] + klo);
            ahf[fm][1] = *(const uint32_t*)(aRowH[fm] + a8 + klo);
            ahf[fm][2] = *(const uint32_t*)(aRowH[fm] + khi);
            ahf[fm][3] = *(const uint32_t*)(aRowH[fm] + a8 + khi);
            alf[fm][0] = *(const uint32_t*)(aRowL[fm] + klo);
            alf[fm][1] = *(const uint32_t*)(aRowL[fm] + a8 + klo);
            alf[fm][2] = *(const uint32_t*)(aRowL[fm] + khi);
            alf[fm][3] = *(const uint32_t*)(aRowL[fm] + a8 + khi);
        }
#pragma unroll
        for (int fn = 0; fn < 4; fn++) {
            bhf[fn][0] = *(const uint32_t*)(bRowH[fn] + klo);
            bhf[fn][1] = *(const uint32_t*)(bRowH[fn] + khi);
            blf[fn][0] = *(const uint32_t*)(bRowL[fn] + klo);
            blf[fn][1] = *(const uint32_t*)(bRowL[fn] + khi);
        }
#pragma unroll
        for (int fm = 0; fm < 4; fm++)
#pragma unroll
            for (int fn = 0; fn < 4; fn++) {
                mma16816(acc[fm][fn], ahf[fm], bhf[fn]);
                mma16816(acc[fm][fn], alf[fm], bhf[fn]);
                mma16816(acc[fm][fn], ahf[fm], blf[fn]);
            }
    }

    // ---- epilogue: c0,c1 @ (g, 2t, 2t+1); c2,c3 @ (g+8, same cols) ----
    const int crow = lane >> 2;
    const int ccol = (lane & 3) * 2;
#pragma unroll
    for (int fm = 0; fm < 4; fm++) {
        const long r1 = row0 + mb + fm * 16 + crow;
        const long r2 = r1 + 8;
#pragma unroll
        for (int fn = 0; fn < 4; fn++) {
            const long cc = col0 + nb + fn * 8 + ccol;
            float v0 = acc[fm][fn][0], v1 = acc[fm][fn][1];
            float v2 = acc[fm][fn][2], v3 = acc[fm][fn][3];
            if (split) {
                __nv_bfloat16 h0 = __float2bfloat16(v0);
                __nv_bfloat16 h1 = __float2bfloat16(v1);
                __nv_bfloat16 h2 = __float2bfloat16(v2);
                __nv_bfloat16 h3 = __float2bfloat16(v3);
                uint32_t p01 = (uint32_t)__bfloat16_as_ushort(h0) |
                               ((uint32_t)__bfloat16_as_ushort(h1) << 16);
                uint32_t p23 = (uint32_t)__bfloat16_as_ushort(h2) |
                               ((uint32_t)__bfloat16_as_ushort(h3) << 16);
                __nv_bfloat16 l0 = __float2bfloat16(v0 - __bfloat162float(h0));
                __nv_bfloat16 l1 = __float2bfloat16(v1 - __bfloat162float(h1));
                __nv_bfloat16 l2 = __float2bfloat16(v2 - __bfloat162float(h2));
                __nv_bfloat16 l3 = __float2bfloat16(v3 - __bfloat162float(h3));
                uint32_t q01 = (uint32_t)__bfloat16_as_ushort(l0) |
                               ((uint32_t)__bfloat16_as_ushort(l1) << 16);
                uint32_t q23 = (uint32_t)__bfloat16_as_ushort(l2) |
                               ((uint32_t)__bfloat16_as_ushort(l3) << 16);
                *(uint32_t*)(Ch + r1 * ldc + cc) = p01;
                *(uint32_t*)(Ch + r2 * ldc + cc) = p23;
                *(uint32_t*)(Cl + r1 * ldc + cc) = q01;
                *(uint32_t*)(Cl + r2 * ldc + cc) = q23;
            } else {
                *(float2*)(Cf + r1 * ldc + cc) = make_float2(v0, v1);
                *(float2*)(Cf + r2 * ldc + cc) = make_float2(v2, v3);
            }
        }
    }
}

// ------------------------------ prep kernels -------------------------------
__global__ void split_kernel(const float* __restrict__ in,
                             __nv_bfloat16* __restrict__ oh,
                             __nv_bfloat16* __restrict__ ol, long n)
{
    long i = (long)blockIdx.x * blockDim.x + threadIdx.x;
    if (i >= n) return;
    float v = in[i];
    __nv_bfloat16 h = __float2bfloat16(v);
    oh[i] = h;
    ol[i] = __float2bfloat16(v - __bfloat162float(h));
}

__global__ void split_transpose(const float* __restrict__ in,
                                __nv_bfloat16* __restrict__ oh,
                                __nv_bfloat16* __restrict__ ol, int R, int C)
{
    __shared__ float t[32][33];
    const long bs = (long)blockIdx.z * R * C;
    in += bs; oh += bs; ol += bs;
    const int c0 = blockIdx.x * 32, r0 = blockIdx.y * 32;
#pragma unroll
    for (int rr = threadIdx.y; rr < 32; rr += 8)
        t[rr][threadIdx.x] = in[(long)(r0 + rr) * C + c0 + threadIdx.x];
    __syncthreads();
#pragma unroll
    for (int cc = threadIdx.y; cc < 32; cc += 8) {
        float v = t[threadIdx.x][cc];
        __nv_bfloat16 h = __float2bfloat16(v);
        long o = (long)(c0 + cc) * R + r0 + threadIdx.x;
        oh[o] = h;
        ol[o] = __float2bfloat16(v - __bfloat162float(h));
    }
}

__global__ void pair_transpose(const __nv_bfloat16* __restrict__ ih,
                               const __nv_bfloat16* __restrict__ il,
                               __nv_bfloat16* __restrict__ oh,
                               __nv_bfloat16* __restrict__ ol, int R, int C)
{
    __shared__ __nv_bfloat16 th[32][33];
    __shared__ __nv_bfloat16 tl[32][33];
    const long bs = (long)blockIdx.z * R * C;
    ih += bs; il += bs; oh += bs; ol += bs;
    const int c0 = blockIdx.x * 32, r0 = blockIdx.y * 32;
#pragma unroll
    for (int rr = threadIdx.y; rr < 32; rr += 8) {
        long idx = (long)(r0 + rr) * C + c0 + threadIdx.x;
        th[rr][threadIdx.x] = ih[idx];
        tl[rr][threadIdx.x] = il[idx];
    }
    __syncthreads();
#pragma unroll
    for (int cc = threadIdx.y; cc < 32; cc += 8) {
        long o = (long)(c0 + cc) * R + r0 + threadIdx.x;
        oh[o] = th[threadIdx.x][cc];
        ol[o] = tl[threadIdx.x][cc];
    }
}

__global__ void colsoftmax_tc()
{
    const int z = blockIdx.y;
    const int j = blockIdx.x * blockDim.x + threadIdx.x;
    const float* S = g_S + (long)z * 1048576;
    __nv_bfloat16* Ph = g_Phi + (long)z * 1048576;
    __nv_bfloat16* Pl = g_Plo + (long)z * 1048576;
    const float scale = 0.03125f;

    float m = -3.402823e38f;
#pragma unroll 8
    for (int i = 0; i < 1024; ++i) m = fmaxf(m, S[i * 1024 + j]);
    const float mm = m * scale;

    float s = 0.0f;
    for (int i = 0; i < 1024; ++i) {
        float t = S[i * 1024 + j] * scale - mm;
        s += (t > -25.0f) ? __expf(t) : 0.0f;
    }
    const float inv = 1.0f / s;

    for (int i = 0; i < 1024; ++i) {
        float t = S[i * 1024 + j] * scale - mm;
        float p = ((t > -25.0f) ? __expf(t) : 0.0f) * inv;
        __nv_bfloat16 h = __float2bfloat16(p);
        Ph[i * 1024 + j] = h;
        Pl[i * 1024 + j] = __float2bfloat16(p - __bfloat162float(h));
    }
}

// -------- numerical check of stage-0 V + buffer probe ----------------------
__global__ void check_kernel(const float* __restrict__ x,
                             const float* __restrict__ WV)
{
    __shared__ int bad, badbuf;
    if (threadIdx.x == 0) { bad = 0; badbuf = 0; }
    __syncthreads();
    const int r = (threadIdx.x * 37) & 127;
    const int v = (threadIdx.x * 97) % 768;
    float ref = 0.0f, refB = 0.0f;
    for (int k = 0; k < 768; k++) {
        ref += x[r * 768 + k] * WV[k * 768 + v];
        float xa = __bfloat162float(g_xhi[r * 768 + k]) +
                   __bfloat162float(g_xlo[r * 768 + k]);
        float wb = __bfloat162float(g_WVth[(long)v * 768 + k]) +
                   __bfloat162float(g_WVtl[(long)v * 768 + k]);
        refB += xa * wb;
    }
    float got = __bfloat162float(g_Vhi[r * 768 + v]) +
                __bfloat162float(g_Vlo[r * 768 + v]);
    float den = fmaxf(fabsf(ref), 1.0f);
    if (fabsf(got - ref) / den > 3e-2f) bad = 1;
    if (fabsf(refB - ref) / den > 3e-2f) badbuf = 1;
    __syncthreads();
    if (threadIdx.x == 0) {
        g_ok = bad ? 0 : 1;
        g_diag_buf = badbuf;
    }
}

// -------- mma unit tests (1 warp, basis vectors) ---------------------------
__global__ void diag_mma()
{
    const int lane = threadIdx.x & 31;
    const uint32_t ONE2 = 0x3F803F80u;   // {bf16 1.0, bf16 1.0}
    const uint32_t ONElo = 0x00003F80u;  // {bf16 1.0, 0}
    int res = 0;
    {   // T1: all ones -> every c == 16
        uint32_t a[4] = {ONE2, ONE2, ONE2, ONE2}, b[2] = {ONE2, ONE2};
        float c[4] = {0, 0, 0, 0};
        mma16816(c, a, b);
        bool ok = fabsf(c[0] - 16.f) < 0.5f && fabsf(c[1] - 16.f) < 0.5f &&
                  fabsf(c[2] - 16.f) < 0.5f && fabsf(c[3] - 16.f) < 0.5f;
        if (!__all_sync(0xffffffffu, ok)) res |= 2;
    }
    {   // T2: A=e(0,0), B=e(k0,n0) -> c0(lane0)=1, all else 0
        uint32_t a[4] = {0, 0, 0, 0}, b[2] = {0, 0};
        if (lane == 0) { a[0] = ONElo; b[0] = ONElo; }
        float c[4] = {0, 0, 0, 0};
        mma16816(c, a, b);
        bool ok;
        if (lane == 0)
            ok = fabsf(c[0] - 1.f) < 1e-3f && fabsf(c[1]) < 1e-3f &&
                 fabsf(c[2]) < 1e-3f && fabsf(c[3]) < 1e-3f;
        else
            ok = fabsf(c[0]) < 1e-3f && fabsf(c[1]) < 1e-3f &&
                 fabsf(c[2]) < 1e-3f && fabsf(c[3]) < 1e-3f;
        if (!__all_sync(0xffffffffu, ok)) res |= 4;
    }
    {   // T3: A=e(8,0) via a1 -> c2(lane0)=1
        uint32_t a[4] = {0, 0, 0, 0}, b[2] = {0, 0};
        if (lane == 0) { a[1] = ONElo; b[0] = ONElo; }
        float c[4] = {0, 0, 0, 0};
        mma16816(c, a, b);
        bool ok = (lane == 0) ? (fabsf(c[2] - 1.f) < 1e-3f && fabsf(c[0]) < 1e-3f)
                              : (fabsf(c[0]) < 1e-3f && fabsf(c[2]) < 1e-3f);
        if (!__all_sync(0xffffffffu, ok)) res |= 8;
        // T4: A=e(0,8) via a2, B k+8 via b1 -> c0(lane0)=1
        uint32_t a2[4] = {0, 0, 0, 0}, b2[2] = {0, 0};
        if (lane == 0) { a2[2] = ONElo; b2[1] = ONElo; }
        float c2[4] = {0, 0, 0, 0};
        mma16816(c2, a2, b2);
        bool ok2 = (lane == 0) ? (fabsf(c2[0] - 1.f) < 1e-3f) : (fabsf(c2[0]) < 1e-3f);
        if (!__all_sync(0xffffffffu, ok2)) res |= 8;
    }
    if (lane == 0) g_diag_mma = res;
}

// -------- duration-encoded telemetry (fires only when guard fired) ---------
__global__ void delay_kernel(int sel, long long cyc)
{
    if (g_ok) return;
    bool fire;
    if (sel == 0) fire = (g_diag_buf != 0);
    else          fire = (g_diag_mma & sel) != 0;
    if (!fire) return;
    long long s = clock64();
    while (clock64() - s < cyc) { }
}

// ===================== SIMT fp32 fallback (proven) =========================
#define BM 128
#define BN 128
#define BK 8

__global__ __launch_bounds__(256, 2)
void simt_gemm(int mode,
               const float* __restrict__ x,
               const float* __restrict__ WQ,
               const float* __restrict__ WK,
               const float* __restrict__ WV,
               const float* __restrict__ WO,
               float* __restrict__ out)
{
    if (g_ok) return;

    const float* A;
    const float* B;
    float* C;
    int lda, ldb, ldc, K;
    const int z = blockIdx.z;

    if (mode == 0) {
        int which = z / 12;
        int h = z - which * 12;
        A = x;  lda = 768;  K = 768;
        const float* Wb = (which == 0) ? WQ : (which == 1) ? WK : WV;
        B = Wb + h * 589824;  ldb = 768;
        float* Ob = (which == 0) ? g_Qf : (which == 1) ? g_Kf : g_Vf;
        C = Ob + h * 6291456; ldc = 768;
    } else if (mode == 1) {
        A = g_Qf + z * 786432; lda = 768;  K = 768;
        B = g_Kf + z * 786432; ldb = 1024;
        C = g_S + (long)z * 1048576; ldc = 1024;
    } else if (mode == 2) {
        int h = z >> 3, b = z & 7;
        A = g_S + (long)z * 1048576; lda = 1024; K = 1024;
        B = g_Vf + z * 786432;  ldb = 768;
        C = g_Zf + b * 9437184 + h * 786432; ldc = 768;
    } else {
        A = g_Zf; lda = 9216; K = 9216;
        B = WO;  ldb = 768;
        C = out; ldc = 768;
    }

    __shared__ float As[2][BK][BM];
    __shared__ float Bs[2][BK][BN];

    const int tid  = threadIdx.x;
    const int row0 = blockIdx.y * BM;
    const int col0 = blockIdx.x * BN;

    const int arow = tid >> 1;
    const int acol = (tid & 1) << 2;
    const int brow = tid >> 5;
    const int bcol = (tid & 31) << 2;

    const float* Aptr = A + (long)(row0 + arow) * lda + acol;
    const float* Bptr = B + (long)brow * ldb + col0 + bcol;

    const int rowb = (tid >> 4) << 3;
    const int colb = (tid & 15) << 3;

    float acc[8][8];
#pragma unroll
    for (int i = 0; i < 8; i++)
#pragma unroll
        for (int j = 0; j < 8; j++) acc[i][j] = 0.0f;

    float4 a4 = *(const float4*)(Aptr);
    float4 b4 = *(const float4*)(Bptr);
    As[0][acol + 0][arow] = a4.x;
    As[0][acol + 1][arow] = a4.y;
    As[0][acol + 2][arow] = a4.z;
    As[0][acol + 3][arow] = a4.w;
    *(float4*)&Bs[0][brow][bcol] = b4;
    __syncthreads();

    const int nIter = K / BK;
    for (int it = 0; it < nIter; ++it) {
        const int cur = it & 1;
        const bool more = (it + 1) < nIter;
        if (more) {
            a4 = *(const float4*)(Aptr + (it + 1) * BK);
            b4 = *(const float4*)(Bptr + (long)(it + 1) * BK * ldb);
        }
#pragma unroll
        for (int kk = 0; kk < BK; ++kk) {
            float ar[8], br[8];
            *(float4*)&ar[0] = *(const float4*)&As[cur][kk][rowb];
            *(float4*)&ar[4] = *(const float4*)&As[cur][kk][rowb + 4];
            *(float4*)&br[0] = *(const float4*)&Bs[cur][kk][colb];
            *(float4*)&br[4] = *(const float4*)&Bs[cur][kk][colb + 4];
#pragma unroll
            for (int i = 0; i < 8; i++)
#pragma unroll
                for (int j = 0; j < 8; j++)
                    acc[i][j] += ar[i] * br[j];
        }
        if (more) {
            const int nxt = cur ^ 1;
            As[nxt][acol + 0][arow] = a4.x;
            As[nxt][acol + 1][arow] = a4.y;
            As[nxt][acol + 2][arow] = a4.z;
            As[nxt][acol + 3][arow] = a4.w;
            *(float4*)&Bs[nxt][brow][bcol] = b4;
        }
        __syncthreads();
    }

#pragma unroll
    for (int i = 0; i < 8; i++) {
        float* Cp = C + (long)(row0 + rowb + i) * ldc + col0 + colb;
        *(float4*)(Cp)     = make_float4(acc[i][0], acc[i][1], acc[i][2], acc[i][3]);
        *(float4*)(Cp + 4) = make_float4(acc[i][4], acc[i][5], acc[i][6], acc[i][7]);
    }
}

__global__ void simt_softmax()
{
    if (g_ok) return;
    const int z = blockIdx.y;
    const int j = blockIdx.x * blockDim.x + threadIdx.x;
    float* S = g_S + (long)z * 1048576;
    const float scale = 0.03125f;

    float m = -3.402823e38f;
#pragma unroll 8
    for (int i = 0; i < 1024; ++i) m = fmaxf(m, S[i * 1024 + j]);
    const float mm = m * scale;

    float s = 0.0f;
#pragma unroll 8
    for (int i = 0; i < 1024; ++i) s += expf(S[i * 1024 + j] * scale - mm);
    const float inv = 1.0f / s;

#pragma unroll 8
    for (int i = 0; i < 1024; ++i)
        S[i * 1024 + j] = expf(S[i * 1024 + j] * scale - mm) * inv;
}

// --------------------------------- launch ----------------------------------
extern "C" void kernel_launch(void* const* d_in, const int* in_sizes, int n_in,
                              void* d_out, int out_size)
{
    const float* x  = (const float*)d_in[0];
    const float* WQ = (const float*)d_in[1];
    const float* WK = (const float*)d_in[2];
    const float* WV = (const float*)d_in[3];
    const float* WO = (const float*)d_in[4];
    float* out = (float*)d_out;

    // ---------- prep ----------
    {
        long n = 8192L * 768;
        split_kernel<<<(int)((n + 255) / 256), 256>>>(x, g_xhi, g_xlo, n);
    }
    dim3 tb(32, 8);
    split_transpose<<<dim3(24, 24, 12), tb>>>(WQ, g_WQth, g_WQtl, 768, 768);
    split_transpose<<<dim3(24, 24, 12), tb>>>(WK, g_WKth, g_WKtl, 768, 768);
    split_transpose<<<dim3(24, 24, 12), tb>>>(WV, g_WVth, g_WVtl, 768, 768);
    split_transpose<<<dim3(24, 288, 1), tb>>>(WO, g_WOth, g_WOtl, 9216, 768);

    // ---------- tensor-core pipeline (direct-LDG fragments) ----------
    mma_gemm<<<dim3(6, 64, 36), 256>>>(0, out);
    check_kernel<<<1, 256>>>(x, WV);
    diag_mma<<<1, 32>>>();

    pair_transpose<<<dim3(32, 24, 96), tb>>>(g_Khi, g_Klo, g_Kthi, g_Ktlo, 768, 1024);
    pair_transpose<<<dim3(24, 32, 96), tb>>>(g_Vhi, g_Vlo, g_Vthi, g_Vtlo, 1024, 768);

    mma_gemm<<<dim3(8, 8, 96), 256>>>(1, out);
    colsoftmax_tc<<<dim3(4, 96), 256>>>();
    mma_gemm<<<dim3(6, 8, 96), 256>>>(2, out);
    mma_gemm<<<dim3(6, 64, 1), 256>>>(3, out);

    // ---------- telemetry (only fires when guard fired) ----------
    delay_kernel<<<1, 1>>>(0, 6000000LL);    // +3ms: prep buffers wrong
    delay_kernel<<<1, 1>>>(2, 12000000LL);   // +6ms: mma all-ones wrong
    delay_kernel<<<1, 1>>>(4, 24000000LL);   // +12ms: c0 positional wrong
    delay_kernel<<<1, 1>>>(8, 48000000LL);   // +24ms: a1/a2/b1 mapping wrong

    // ---------- guarded SIMT fallback (no-op when g_ok==1) ----------
    simt_gemm<<<dim3(6, 64, 36), 256>>>(0, x, WQ, WK, WV, WO, out);
    simt_gemm<<<dim3(8, 8, 96), 256>>>(1, x, WQ, WK, WV, WO, out);
    simt_softmax<<<dim3(4, 96), 256>>>();
    simt_gemm<<<dim3(6, 8, 96), 256>>>(2, x, WQ, WK, WV, WO, out);
    simt_gemm<<<dim3(6, 64, 1), 256>>>(3, x, WQ, WK, WV, WO, out);
}

// round 13
// speedup vs baseline: 2.7101x; 2.7101x over previous
#include <cuda_runtime.h>
#include <math.h>
#include <cstdint>

// ---------------------------------------------------------------------------
// MultiHeadAttention (B=8, T=1024, E=768, H=12) -- fp32 SIMT pipeline
// (proven round-1 design) with packed fma.rn.f32x2 (FFMA2) inner loop.
//
// Stage 0: Q/K/V[h] = x @ W{Q,K,V}[h]          (36 GEMMs 8192x768x768)
// Stage 1: S[h,b]   = Q[h,b] @ view(K[h,b])    (96 GEMMs 1024x1024x768)
// Stage 2: column softmax of S (axis = query), scale 1/32 folded in
// Stage 3: Z[b][h]  = S[h,b] @ V[h,b]          (96 GEMMs 1024x768x1024)
// Stage 4: out      = view(Z, 8192x9216) @ WO  (1 GEMM 8192x768x9216)
//
// FFMA2: ptxas never auto-fuses packed fp32 FMA from C++ (SASS_QUICKREF);
// we emit fma.rn.f32x2 via inline PTX, packing accumulators along N.
// The portable compute_103 pass compiles the scalar FFMA inner instead.
// ---------------------------------------------------------------------------

#if defined(__CUDA_ARCH__) && (defined(__CUDA_ARCH_FEAT_SM103_ALL) || defined(__CUDA_ARCH_SPECIFIC__))
#define HAS_F32X2 1
#else
#define HAS_F32X2 0
#endif

// scratch (device globals; allocation-free per harness rules)
__device__ float g_Q[12 * 8 * 1024 * 768];   // [h][b][t][k]
__device__ float g_K[12 * 8 * 1024 * 768];   // [h][b][t][k]
__device__ float g_V[12 * 8 * 1024 * 768];   // [h][b][t][v]
__device__ float g_S[12 * 8 * 1024 * 1024];  // [h*8+b][t][t]
__device__ float g_Z[8 * 12 * 1024 * 768];   // [b][h][t][v]

#define BM 128
#define BN 128
#define BK 8

__global__ __launch_bounds__(256, 2)
void gemm_kernel(int mode,
                 const float* __restrict__ x,
                 const float* __restrict__ WQ,
                 const float* __restrict__ WK,
                 const float* __restrict__ WV,
                 const float* __restrict__ WO,
                 float* __restrict__ out)
{
    const float* A;
    const float* B;
    float* C;
    int lda, ldb, ldc, K;
    const int z = blockIdx.z;

    if (mode == 0) {
        // projections: z = which*12 + h ; which 0=Q,1=K,2=V
        int which = z / 12;
        int h = z - which * 12;
        A = x;  lda = 768;  K = 768;
        const float* Wb = (which == 0) ? WQ : (which == 1) ? WK : WV;
        B = Wb + h * 589824;  ldb = 768;                 // 768*768
        float* Ob = (which == 0) ? g_Q : (which == 1) ? g_K : g_V;
        C = Ob + h * 6291456; ldc = 768;                 // 8192*768
    } else if (mode == 1) {
        // scores: z = h*8+b.  B = K's buffer viewed (768 x 1024) row-major.
        A = g_Q + z * 786432; lda = 768;  K = 768;
        B = g_K + z * 786432; ldb = 1024;
        C = g_S + (long)z * 1048576; ldc = 1024;
    } else if (mode == 2) {
        // Z = A @ V, written into [b][h][t][v] layout
        int h = z >> 3, b = z & 7;
        A = g_S + (long)z * 1048576; lda = 1024; K = 1024;
        B = g_V + z * 786432;  ldb = 768;
        C = g_Z + b * 9437184 + h * 786432; ldc = 768;
    } else {
        // out = view(Z) @ WO
        A = g_Z; lda = 9216; K = 9216;
        B = WO;  ldb = 768;
        C = out; ldc = 768;
    }

    __shared__ float As[2][BK][BM];
    __shared__ float Bs[2][BK][BN];

    const int tid  = threadIdx.x;
    const int row0 = blockIdx.y * BM;
    const int col0 = blockIdx.x * BN;

    // global-load mapping
    const int arow = tid >> 1;           // 0..127
    const int acol = (tid & 1) << 2;     // 0 or 4
    const int brow = tid >> 5;           // 0..7
    const int bcol = (tid & 31) << 2;    // 0..124

    const float* Aptr = A + (long)(row0 + arow) * lda + acol;
    const float* Bptr = B + (long)brow * ldb + col0 + bcol;

    // compute mapping: 16x16 threads of 8x8 each
    const int rowb = (tid >> 4) << 3;    // 0..120
    const int colb = (tid & 15) << 3;    // 0..120

#if HAS_F32X2
    // accumulators packed along N: accp[i][j2] holds cols {2j2, 2j2+1}
    unsigned long long accp[8][4];
#pragma unroll
    for (int i = 0; i < 8; i++)
#pragma unroll
        for (int j = 0; j < 4; j++) accp[i][j] = 0ULL;
#else
    float acc[8][8];
#pragma unroll
    for (int i = 0; i < 8; i++)
#pragma unroll
        for (int j = 0; j < 8; j++) acc[i][j] = 0.0f;
#endif

    // prologue: stage k-block 0
    float4 a4 = *(const float4*)(Aptr);
    float4 b4 = *(const float4*)(Bptr);
    As[0][acol + 0][arow] = a4.x;
    As[0][acol + 1][arow] = a4.y;
    As[0][acol + 2][arow] = a4.z;
    As[0][acol + 3][arow] = a4.w;
    *(float4*)&Bs[0][brow][bcol] = b4;
    __syncthreads();

    const int nIter = K / BK;
    for (int it = 0; it < nIter; ++it) {
        const int cur = it & 1;
        const bool more = (it + 1) < nIter;
        if (more) {  // issue next global loads early; latency hides under FMAs
            a4 = *(const float4*)(Aptr + (it + 1) * BK);
            b4 = *(const float4*)(Bptr + (long)(it + 1) * BK * ldb);
        }
#pragma unroll
        for (int kk = 0; kk < BK; ++kk) {
            float ar[8];
            *(float4*)&ar[0] = *(const float4*)&As[cur][kk][rowb];
            *(float4*)&ar[4] = *(const float4*)&As[cur][kk][rowb + 4];
#if HAS_F32X2
            unsigned long long brp[4];
            {
                const unsigned long long* bp =
                    (const unsigned long long*)&Bs[cur][kk][colb];
                brp[0] = bp[0]; brp[1] = bp[1]; brp[2] = bp[2]; brp[3] = bp[3];
            }
#pragma unroll
            for (int i = 0; i < 8; i++) {
                unsigned long long arp;
                asm("mov.b64 %0, {%1, %1};"
                    : "=l"(arp) : "r"(__float_as_uint(ar[i])));
#pragma unroll
                for (int j = 0; j < 4; j++)
                    asm("fma.rn.f32x2 %0, %1, %2, %0;"
                        : "+l"(accp[i][j]) : "l"(arp), "l"(brp[j]));
            }
#else
            float br[8];
            *(float4*)&br[0] = *(const float4*)&Bs[cur][kk][colb];
            *(float4*)&br[4] = *(const float4*)&Bs[cur][kk][colb + 4];
#pragma unroll
            for (int i = 0; i < 8; i++)
#pragma unroll
                for (int j = 0; j < 8; j++)
                    acc[i][j] += ar[i] * br[j];
#endif
        }
        if (more) {
            const int nxt = cur ^ 1;
            As[nxt][acol + 0][arow] = a4.x;
            As[nxt][acol + 1][arow] = a4.y;
            As[nxt][acol + 2][arow] = a4.z;
            As[nxt][acol + 3][arow] = a4.w;
            *(float4*)&Bs[nxt][brow][bcol] = b4;
        }
        __syncthreads();
    }

#if HAS_F32X2
#pragma unroll
    for (int i = 0; i < 8; i++) {
        float* Cp = C + (long)(row0 + rowb + i) * ldc + col0 + colb;
        float v[8];
#pragma unroll
        for (int j = 0; j < 4; j++) {
            uint32_t lo, hi;
            asm("mov.b64 {%0, %1}, %2;" : "=r"(lo), "=r"(hi) : "l"(accp[i][j]));
            v[2 * j]     = __uint_as_float(lo);
            v[2 * j + 1] = __uint_as_float(hi);
        }
        *(float4*)(Cp)     = make_float4(v[0], v[1], v[2], v[3]);
        *(float4*)(Cp + 4) = make_float4(v[4], v[5], v[6], v[7]);
    }
#else
#pragma unroll
    for (int i = 0; i < 8; i++) {
        float* Cp = C + (long)(row0 + rowb + i) * ldc + col0 + colb;
        *(float4*)(Cp)     = make_float4(acc[i][0], acc[i][1], acc[i][2], acc[i][3]);
        *(float4*)(Cp + 4) = make_float4(acc[i][4], acc[i][5], acc[i][6], acc[i][7]);
    }
#endif
}

// Column-wise softmax over the query axis (rows), per key column j.
// Thread-per-column => fully coalesced (columns are the fast axis).
// Scale 1/sqrt(T)=1/32 folded in here.
__global__ void colsoftmax_kernel()
{
    const int z = blockIdx.y;                                  // h*8+b
    const int j = blockIdx.x * blockDim.x + threadIdx.x;       // key column
    float* S = g_S + (long)z * 1048576;
    const float scale = 0.03125f;

    float m = -3.402823e38f;
#pragma unroll 8
    for (int i = 0; i < 1024; ++i) m = fmaxf(m, S[i * 1024 + j]);
    const float mm = m * scale;

    float s = 0.0f;
#pragma unroll 8
    for (int i = 0; i < 1024; ++i) s += expf(S[i * 1024 + j] * scale - mm);
    const float inv = 1.0f / s;

#pragma unroll 8
    for (int i = 0; i < 1024; ++i)
        S[i * 1024 + j] = expf(S[i * 1024 + j] * scale - mm) * inv;
}

extern "C" void kernel_launch(void* const* d_in, const int* in_sizes, int n_in,
                              void* d_out, int out_size)
{
    const float* x  = (const float*)d_in[0];
    const float* WQ = (const float*)d_in[1];
    const float* WK = (const float*)d_in[2];
    const float* WV = (const float*)d_in[3];
    const float* WO = (const float*)d_in[4];
    float* out = (float*)d_out;

    // Stage 0: QKV projections (36 x 8192x768x768)
    gemm_kernel<<<dim3(6, 64, 36), 256>>>(0, x, WQ, WK, WV, WO, out);
    // Stage 1: scores (96 x 1024x1024x768)
    gemm_kernel<<<dim3(8, 8, 96), 256>>>(1, x, WQ, WK, WV, WO, out);
    // Stage 2: column softmax (in place, with 1/32 scaling)
    colsoftmax_kernel<<<dim3(4, 96), 256>>>();
    // Stage 3: Z = A @ V (96 x 1024x768x1024) -> [b][h][t][v]
    gemm_kernel<<<dim3(6, 8, 96), 256>>>(2, x, WQ, WK, WV, WO, out);
    // Stage 4: out = view(Z, 8192x9216) @ WO
    gemm_kernel<<<dim3(6, 64, 1), 256>>>(3, x, WQ, WK, WV, WO, out);
}